// round 15
// baseline (speedup 1.0000x reference)
#include <cuda_runtime.h>
#include <cuda_bf16.h>
#include <cstdint>

#define CDIM    128
#define KTOT    1024
#define MV      128
#define NTL     128
#define NTILES  8
#define HW      4096
#define NTHREADS 256

// dynamic SMEM byte offsets (48KB total -> 2 CTAs/SM easily)
#define SM_SE    0        // 1024 f  exact ||e||^2
#define SM_SE1   4096     // 1024 f  ||e||^2 + 1.0 (key domain)
#define SM_SCL   8192     // 1024 f  2*s_k (codebook int8 scale, premult)
#define SM_VN    12288    // 128 f   ||z||^2
#define SM_SZV   12800    // 128 f   sz_v (z int8 scale)
#define SM_RK    13312    // 128*4 i (early: 128 f rcp z-scale during staging)
#define SM_RNE   15360    // 128 i
#define SM_ZH    16384    // 16KB: int8 A image, then B double-buffer slot 1
#define SM_BH    32768    // 16KB: B double-buffer slot 0
#define SM_TOTAL 49152    // = SM_BH + 16384  (checked: all regions disjoint)

#define RESCUE_EPS 3e-3f

// device scratch (no allocations allowed)
__device__ float  g_enorm[KTOT];
__device__ float  g_scl[KTOT];      // 2*s_k
__device__ int    g_used[KTOT];
__device__ double g_sq;
__device__ __align__(16) int8_t g_cbi8[NTILES][NTL * CDIM];  // swizzled images

__device__ __forceinline__ uint32_t s2u(const void* p) {
    uint32_t a;
    asm("{ .reg .u64 t; cvta.to.shared.u64 t, %1; cvt.u32.u64 %0, t; }" : "=r"(a) : "l"(p));
    return a;
}
__device__ __forceinline__ void cp16(uint32_t saddr, const void* gptr) {
    asm volatile("cp.async.cg.shared.global [%0], [%1], 16;"
                 :: "r"(saddr), "l"(gptr) : "memory");
}
__device__ __forceinline__ void cp_commit() {
    asm volatile("cp.async.commit_group;" ::: "memory");
}
template<int N>
__device__ __forceinline__ void cp_wait() {
    asm volatile("cp.async.wait_group %0;" :: "n"(N) : "memory");
}

// byte offset of (row r, byte-col c) in a 128x128-byte tile image, 128B/row,
// 16B chunks XOR-swizzled so ldmatrix (8 rows, same chunk) is conflict-free
__device__ __forceinline__ int toff8(int r, int c) {
    return r * 128 + (((c >> 4) ^ (r & 7)) << 4) + (c & 15);
}

// monotone key: positive-float score bits (top 22) | code index (low 10)
__device__ __forceinline__ uint32_t mkkey(float r, int code) {
    return (__float_as_uint(r) & 0xFFFFFC00u) | (uint32_t)code;
}
// branch-free sorted-4 insertion (b1 <= b2 <= b3 <= b4)
__device__ __forceinline__ void ins4(uint32_t k, uint32_t& b1, uint32_t& b2,
                                     uint32_t& b3, uint32_t& b4) {
    uint32_t t;
    t = umax(k, b1); b1 = umin(k, b1); k = t;
    t = umax(k, b2); b2 = umin(k, b2); k = t;
    t = umax(k, b3); b3 = umin(k, b3); k = t;
    b4 = umin(k, b4);
}
#define GINS4(key, b1, b2, b3, b4) do { \
    uint32_t _k = (key); \
    if (_k < (b4)) ins4(_k, b1, b2, b3, b4); \
} while (0)

// ---------------------------------------------------------------------------
// Kernel 1: prep — enorm, int8 scales, resets, swizzled int8 codebook image
// ---------------------------------------------------------------------------
__global__ void vq_prep(const float* __restrict__ cb) {
    int w    = threadIdx.x >> 5;
    int lane = threadIdx.x & 31;
    int k    = blockIdx.x * 4 + w;              // 0..1023
    int c    = lane << 2;

    float4 v = ((const float4*)(cb + (size_t)k * CDIM))[lane];
    float s = __fmaf_rn(v.x, v.x, 0.f);
    s = __fmaf_rn(v.y, v.y, s);
    s = __fmaf_rn(v.z, v.z, s);
    s = __fmaf_rn(v.w, v.w, s);
    #pragma unroll
    for (int off = 16; off; off >>= 1)
        s = __fadd_rn(s, __shfl_down_sync(0xffffffffu, s, off));

    // row max |e| (all lanes)
    float m = fmaxf(fmaxf(fabsf(v.x), fabsf(v.y)), fmaxf(fabsf(v.z), fabsf(v.w)));
    #pragma unroll
    for (int off = 16; off; off >>= 1)
        m = fmaxf(m, __shfl_xor_sync(0xffffffffu, m, off));
    m = fmaxf(m, 1e-30f);
    float rcp = 127.0f / m;

    int xi0 = __float2int_rn(v.x * rcp);
    int xi1 = __float2int_rn(v.y * rcp);
    int xi2 = __float2int_rn(v.z * rcp);
    int xi3 = __float2int_rn(v.w * rcp);
    uint32_t packed = (uint32_t)(xi0 & 255) | ((uint32_t)(xi1 & 255) << 8)
                    | ((uint32_t)(xi2 & 255) << 16) | ((uint32_t)(xi3 & 255) << 24);

    int nt = k >> 7, r = k & 127;
    *(uint32_t*)((uint8_t*)g_cbi8[nt] + toff8(r, c)) = packed;

    if (lane == 0) {
        g_enorm[k] = s;
        g_scl[k]   = m * (2.0f / 127.0f);       // 2*s_k
        g_used[k]  = 0;
        if (k == 0) g_sq = 0.0;
    }
}

// ---------------------------------------------------------------------------
// Kernel 2: main — s8 IMMA m16n8k32 GEMM, cp.async double-buffered B,
//           keyed top-4 + exact 4-way rescue (reference fp32 chain)
// ---------------------------------------------------------------------------
__global__ void __launch_bounds__(NTHREADS, 2) vq_mma(
    const float* __restrict__ z, const float* __restrict__ cb,
    float* __restrict__ out)
{
    extern __shared__ char smem[];
    const uint32_t sb = s2u(smem);
    const int tid  = threadIdx.x;
    const int w    = tid >> 5;
    const int lane = tid & 31;
    const int g    = lane >> 2;
    const int tg   = lane & 3;
    const int m0   = w << 4;

    float* se   = (float*)(smem + SM_SE);
    float* se1  = (float*)(smem + SM_SE1);
    float* scl  = (float*)(smem + SM_SCL);
    float* vna  = (float*)(smem + SM_VN);
    float* szva = (float*)(smem + SM_SZV);
    int*   rk   = (int*)(smem + SM_RK);
    int*   rne  = (int*)(smem + SM_RNE);
    float* rscl = (float*)(smem + SM_RK);   // staging-phase overlay (dead before rk use)

    #pragma unroll
    for (int i = tid; i < KTOT; i += NTHREADS) {
        float e = g_enorm[i];
        se[i]  = e;
        se1[i] = __fadd_rn(e, 1.0f);
        scl[i] = g_scl[i];
    }

    // ---- kick off async copy of B tile 0 into SM_BH (16KB) ----
    {
        const char* src = (const char*)g_cbi8[0] + tid * 16;
        uint32_t dst = sb + SM_BH + tid * 16;
        #pragma unroll
        for (int i = 0; i < 4; ++i)
            cp16(dst + i * 4096, src + i * 4096);
        cp_commit();
    }

    const int n0 = blockIdx.x * MV;
    const int b  = n0 >> 12;
    const int p0 = n0 & (HW - 1);
    const float* zb = z + (size_t)b * CDIM * HW + p0;

    // ---- ||z||^2 + max|z| per vector (exact ascending chain for vn) ----
    if (tid < MV) {
        float s = 0.f, mx = 0.f;
        #pragma unroll 8
        for (int c = 0; c < CDIM; ++c) {
            float x = zb[(size_t)c * HW + tid];
            s = __fmaf_rn(x, x, s);
            mx = fmaxf(mx, fabsf(x));
        }
        mx = fmaxf(mx, 1e-30f);
        vna[tid]  = s;
        szva[tid] = mx * (1.0f / 127.0f);
        rscl[tid] = 127.0f / mx;
    }
    __syncthreads();

    // ---- stage z: quantize to int8 swizzled A image (16KB) ----
    uint8_t* zh = (uint8_t*)smem + SM_ZH;
    {
        int v = tid & 127;
        int cg0 = tid >> 7;                     // 0 or 1
        float rcp = rscl[v];
        #pragma unroll 4
        for (int i = 0; i < 16; ++i) {
            int c = (cg0 + i * 2) * 4;          // byte col, multiple of 4
            int x0 = __float2int_rn(zb[(size_t)(c + 0) * HW + v] * rcp);
            int x1 = __float2int_rn(zb[(size_t)(c + 1) * HW + v] * rcp);
            int x2 = __float2int_rn(zb[(size_t)(c + 2) * HW + v] * rcp);
            int x3 = __float2int_rn(zb[(size_t)(c + 3) * HW + v] * rcp);
            uint32_t packed = (uint32_t)(x0 & 255) | ((uint32_t)(x1 & 255) << 8)
                            | ((uint32_t)(x2 & 255) << 16) | ((uint32_t)(x3 & 255) << 24);
            *(uint32_t*)(zh + toff8(v, c)) = packed;
        }
    }
    __syncthreads();

    // ---- load A fragments ONCE: 4 x ldmatrix.x4 (s8 m16n8k32 layout) ----
    uint32_t afr[4][4];
    {
        int mat = lane >> 3;
        int ar  = m0 + (lane & 7) + ((mat & 1) << 3);
        uint32_t arow = sb + SM_ZH + ar * 128;
        #pragma unroll
        for (int kk = 0; kk < 4; ++kk) {
            int ac = (kk << 1) + (mat >> 1);    // 16B chunk idx
            uint32_t aaddr = arow + (((ac ^ (ar & 7))) << 4);
            asm volatile(
                "ldmatrix.sync.aligned.m8n8.x4.shared.b16 {%0,%1,%2,%3}, [%4];"
                : "=r"(afr[kk][0]), "=r"(afr[kk][1]),
                  "=r"(afr[kk][2]), "=r"(afr[kk][3]) : "r"(aaddr));
        }
    }
    __syncthreads();   // ZH free: becomes B double-buffer slot 1

    const float szL = szva[m0 + g];
    const float szH = szva[m0 + g + 8];

    uint32_t L1 = 0xFFFFFFFFu, L2 = 0xFFFFFFFFu, L3 = 0xFFFFFFFFu, L4 = 0xFFFFFFFFu;
    uint32_t H1 = 0xFFFFFFFFu, H2 = 0xFFFFFFFFu, H3 = 0xFFFFFFFFu, H4 = 0xFFFFFFFFu;

    const int b_jhalf = (lane >> 4) & 1;
    const int b_kpar  = (lane >> 3) & 1;
    const int b_row   = lane & 7;
    const uint32_t bufb[2] = { sb + SM_BH, sb + SM_ZH };

    for (int nt = 0; nt < NTILES; ++nt) {
        if (nt < NTILES - 1) {
            const char* src = (const char*)g_cbi8[nt + 1] + tid * 16;
            uint32_t dst = bufb[(nt + 1) & 1] + tid * 16;
            #pragma unroll
            for (int i = 0; i < 4; ++i)
                cp16(dst + i * 4096, src + i * 4096);
            cp_commit();
            cp_wait<1>();
        } else {
            cp_wait<0>();
        }
        __syncthreads();

        const uint32_t Bb = bufb[nt & 1];

        #pragma unroll 1
        for (int g32 = 0; g32 < 4; ++g32) {     // 32 codes per group
            int acc[4][4];
            #pragma unroll
            for (int j = 0; j < 4; ++j)
                #pragma unroll
                for (int q = 0; q < 4; ++q) acc[j][q] = 0;

            // load all B frags: 4 kk-steps x 2 j-pairs via 8 ldmatrix.x4
            uint32_t bf[4][2][4];
            #pragma unroll
            for (int kk = 0; kk < 4; ++kk) {
                int bc = (kk << 1) + b_kpar;
                #pragma unroll
                for (int jp = 0; jp < 2; ++jp) {
                    int br = (g32 << 5) + (jp << 4) + (b_jhalf << 3) + b_row;
                    uint32_t baddr = Bb + br * 128 + (((bc ^ (br & 7))) << 4);
                    asm volatile(
                        "ldmatrix.sync.aligned.m8n8.x4.shared.b16 {%0,%1,%2,%3}, [%4];"
                        : "=r"(bf[kk][jp][0]), "=r"(bf[kk][jp][1]),
                          "=r"(bf[kk][jp][2]), "=r"(bf[kk][jp][3]) : "r"(baddr));
                }
            }
            // 16 IMMA, 4 independent acc chains
            #pragma unroll
            for (int kk = 0; kk < 4; ++kk) {
                #pragma unroll
                for (int j = 0; j < 4; ++j) {
                    const uint32_t* bp = &bf[kk][j >> 1][(j & 1) << 1];
                    asm volatile(
                        "mma.sync.aligned.m16n8k32.row.col.s32.s8.s8.s32 "
                        "{%0,%1,%2,%3}, {%4,%5,%6,%7}, {%8,%9}, {%0,%1,%2,%3};"
                        : "+r"(acc[j][0]), "+r"(acc[j][1]),
                          "+r"(acc[j][2]), "+r"(acc[j][3])
                        : "r"(afr[kk][0]), "r"(afr[kk][1]),
                          "r"(afr[kk][2]), "r"(afr[kk][3]),
                          "r"(bp[0]), "r"(bp[1]));
                }
            }

            // ---- keyed approx ranking: r = (se+1) - sz_v*(2 s_k)*dotint ----
            int kgb = nt * NTL + (g32 << 5);
            #pragma unroll
            for (int j = 0; j < 4; ++j) {
                int c0 = kgb + (j << 3) + (tg << 1);
                float s0 = se1[c0], s1 = se1[c0 + 1];
                float q0 = scl[c0], q1 = scl[c0 + 1];
                float f0 = (float)acc[j][0], f1 = (float)acc[j][1];
                float f2 = (float)acc[j][2], f3 = (float)acc[j][3];
                GINS4(mkkey(__fmaf_rn(-szL, __fmul_rn(q0, f0), s0), c0),     L1, L2, L3, L4);
                GINS4(mkkey(__fmaf_rn(-szL, __fmul_rn(q1, f1), s1), c0 + 1), L1, L2, L3, L4);
                GINS4(mkkey(__fmaf_rn(-szH, __fmul_rn(q0, f2), s0), c0),     H1, H2, H3, H4);
                GINS4(mkkey(__fmaf_rn(-szH, __fmul_rn(q1, f3), s1), c0 + 1), H1, H2, H3, H4);
            }
        }
        __syncthreads();    // all warps done reading this buffer before overwrite
    }

    // ---- merge top-4 across the 4 lanes of each quad ----
    #pragma unroll
    for (int d = 1; d <= 2; d <<= 1) {
        uint32_t o1 = __shfl_xor_sync(0xffffffffu, L1, d);
        uint32_t o2 = __shfl_xor_sync(0xffffffffu, L2, d);
        uint32_t o3 = __shfl_xor_sync(0xffffffffu, L3, d);
        uint32_t o4 = __shfl_xor_sync(0xffffffffu, L4, d);
        ins4(o1, L1, L2, L3, L4); ins4(o2, L1, L2, L3, L4);
        ins4(o3, L1, L2, L3, L4); ins4(o4, L1, L2, L3, L4);
        o1 = __shfl_xor_sync(0xffffffffu, H1, d);
        o2 = __shfl_xor_sync(0xffffffffu, H2, d);
        o3 = __shfl_xor_sync(0xffffffffu, H3, d);
        o4 = __shfl_xor_sync(0xffffffffu, H4, d);
        ins4(o1, H1, H2, H3, H4); ins4(o2, H1, H2, H3, H4);
        ins4(o3, H1, H2, H3, H4); ins4(o4, H1, H2, H3, H4);
    }
    if (tg == 0) {
        int rL = m0 + g, rH = m0 + g + 8;
        rk[rL * 4 + 0] = L1 & 1023; rk[rL * 4 + 1] = L2 & 1023;
        rk[rL * 4 + 2] = L3 & 1023; rk[rL * 4 + 3] = L4 & 1023;
        rk[rH * 4 + 0] = H1 & 1023; rk[rH * 4 + 1] = H2 & 1023;
        rk[rH * 4 + 2] = H3 & 1023; rk[rH * 4 + 3] = H4 & 1023;
        float sL1 = __uint_as_float(L1 & 0xFFFFFC00u);
        float sL2 = __uint_as_float(L2 & 0xFFFFFC00u);
        float sH1 = __uint_as_float(H1 & 0xFFFFFC00u);
        float sH2 = __uint_as_float(H2 & 0xFFFFFC00u);
        rne[rL] = (__fsub_rn(sL2, sL1) <= RESCUE_EPS);
        rne[rH] = (__fsub_rn(sH2, sH1) <= RESCUE_EPS);
    }
    __syncthreads();

    // ---- exact 4-way rescue (reference fp32 chain, z from GMEM) + output ----
    float errsum = 0.f;
    if (tid < MV) {
        int v = tid;
        int kb = rk[v * 4];
        if (rne[v]) {
            int k0 = rk[v * 4], k1 = rk[v * 4 + 1],
                k2 = rk[v * 4 + 2], k3 = rk[v * 4 + 3];
            const float* r0 = cb + (size_t)k0 * CDIM;
            const float* r1 = cb + (size_t)k1 * CDIM;
            const float* r2 = cb + (size_t)k2 * CDIM;
            const float* r3 = cb + (size_t)k3 * CDIM;
            float d0 = 0.f, d1 = 0.f, d2 = 0.f, d3 = 0.f;
            #pragma unroll 8
            for (int c = 0; c < CDIM; ++c) {
                float zv = zb[(size_t)c * HW + v];
                d0 = __fmaf_rn(zv, r0[c], d0);
                d1 = __fmaf_rn(zv, r1[c], d1);
                d2 = __fmaf_rn(zv, r2[c], d2);
                d3 = __fmaf_rn(zv, r3[c], d3);
            }
            float vn = vna[v];
            float e0 = __fsub_rn(__fadd_rn(vn, se[k0]), __fmul_rn(2.0f, d0));
            float e1 = __fsub_rn(__fadd_rn(vn, se[k1]), __fmul_rn(2.0f, d1));
            float e2 = __fsub_rn(__fadd_rn(vn, se[k2]), __fmul_rn(2.0f, d2));
            float e3 = __fsub_rn(__fadd_rn(vn, se[k3]), __fmul_rn(2.0f, d3));
            float bd = e0; kb = k0;
            if (e1 < bd || (e1 == bd && k1 < kb)) { bd = e1; kb = k1; }
            if (e2 < bd || (e2 == bd && k2 < kb)) { bd = e2; kb = k2; }
            if (e3 < bd || (e3 == bd && k3 < kb)) { bd = e3; kb = k3; }
        }
        g_used[kb] = 1;

        // z_q_st = fl(z + fl(z_q - z)) in (B,C,H,W); MSE partial
        const float4* crow = (const float4*)(cb + (size_t)kb * CDIM);
        float* ob = out + (size_t)b * CDIM * HW + p0 + v;
        #pragma unroll 4
        for (int c4 = 0; c4 < 32; ++c4) {
            float4 e4 = crow[c4];
            float ee[4] = {e4.x, e4.y, e4.z, e4.w};
            #pragma unroll
            for (int jj = 0; jj < 4; ++jj) {
                int c = c4 * 4 + jj;
                float zv = zb[(size_t)c * HW + v];
                float t  = __fsub_rn(ee[jj], zv);
                ob[(size_t)c * HW] = __fadd_rn(zv, t);
                errsum = __fmaf_rn(t, t, errsum);
            }
        }
    }

    // ---- block reduce squared error -> double atomic ----
    __syncthreads();
    float* red = (float*)(smem + SM_SE);
    if (tid < MV) red[tid] = errsum;
    __syncthreads();
    if (tid < 64) red[tid] = __fadd_rn(red[tid], red[tid + 64]);
    __syncthreads();
    if (tid < 32) {
        float s = __fadd_rn(red[tid], red[tid + 32]);
        #pragma unroll
        for (int off = 16; off; off >>= 1)
            s = __fadd_rn(s, __shfl_down_sync(0xffffffffu, s, off));
        if (tid == 0) atomicAdd(&g_sq, (double)s);
    }
}

// ---------------------------------------------------------------------------
// Kernel 3: finalize — vq_loss + usage scalars
// ---------------------------------------------------------------------------
__global__ void vq_fin(float* __restrict__ out, int npix) {
    __shared__ int cnt[32];
    int tid = threadIdx.x;             // 1024 threads
    int u = g_used[tid] ? 1 : 0;
    #pragma unroll
    for (int off = 16; off; off >>= 1) u += __shfl_down_sync(0xffffffffu, u, off);
    if ((tid & 31) == 0) cnt[tid >> 5] = u;
    __syncthreads();
    if (tid == 0) {
        int total = 0;
        #pragma unroll
        for (int i = 0; i < 32; ++i) total += cnt[i];
        float m  = (float)(g_sq / (double)npix);
        float vq = __fadd_rn(m, __fmul_rn(0.25f, m));
        out[npix]     = vq;
        out[npix + 1] = (float)total * (1.0f / 1024.0f);
    }
}

// ---------------------------------------------------------------------------
extern "C" void kernel_launch(void* const* d_in, const int* in_sizes, int n_in,
                              void* d_out, int out_size) {
    const float* z  = (const float*)d_in[0];
    const float* cb = (const float*)d_in[1];
    float* out = (float*)d_out;
    int npix = out_size - 2;                    // 8388608
    int nvec = npix / CDIM;                     // 65536
    int blocks = nvec / MV;                     // 512

    cudaFuncSetAttribute(vq_mma, cudaFuncAttributeMaxDynamicSharedMemorySize, SM_TOTAL);

    vq_prep<<<KTOT / 4, 128>>>(cb);
    vq_mma<<<blocks, NTHREADS, SM_TOTAL>>>(z, cb, out);
    vq_fin<<<1, KTOT>>>(out, npix);
}

// round 16
// speedup vs baseline: 1.3301x; 1.3301x over previous
#include <cuda_runtime.h>
#include <cuda_bf16.h>
#include <cstdint>

#define CDIM    128
#define KTOT    1024
#define MV      128
#define NTL     128
#define NTILES  8
#define HW      4096
#define NTHREADS 256

// dynamic SMEM byte offsets (44KB total -> 3 CTAs/SM)
#define SM_SE    0        // 1024 f  exact ||e||^2
#define SM_SE1   4096     // 1024 f  ||e||^2 + 1.0 (key domain)
#define SM_VN    8192     // 128 f
#define SM_RK    8704     // 128*4 i  candidate indices
#define SM_RNE   10752    // 128 i    rescue flags
#define SM_AB    11264    // 32KB: A-tile image first, then per-tile B buffer
#define SM_TOTAL 44032    // = SM_AB + 32768 (regions disjoint, sum checked)

#define RESCUE_EPS 2e-3f

// device scratch (no allocations allowed)
__device__ float  g_enorm[KTOT];
__device__ int    g_used[KTOT];
__device__ double g_sq;
__device__ __align__(16) __nv_bfloat16 g_cbh[NTILES][NTL * CDIM];  // swizzled images

__device__ __forceinline__ uint32_t s2u(const void* p) {
    uint32_t a;
    asm("{ .reg .u64 t; cvta.to.shared.u64 t, %1; cvt.u32.u64 %0, t; }" : "=r"(a) : "l"(p));
    return a;
}

// byte offset of (row r, k-col c) in a 128x128-bf16 tile image, 256B/row,
// 16B chunks XOR-swizzled so ldmatrix (8 rows, same chunk) is conflict-free
__device__ __forceinline__ int toff(int r, int c) {
    return r * 256 + (((c >> 3) ^ (r & 7)) << 4) + ((c & 7) << 1);
}

// monotone key: positive-float score bits (top 22) | code index (low 10)
__device__ __forceinline__ uint32_t mkkey(float r, int code) {
    return (__float_as_uint(r) & 0xFFFFFC00u) | (uint32_t)code;
}
// branch-free sorted-4 insertion (b1 <= b2 <= b3 <= b4)
__device__ __forceinline__ void ins4(uint32_t k, uint32_t& b1, uint32_t& b2,
                                     uint32_t& b3, uint32_t& b4) {
    uint32_t t;
    t = umax(k, b1); b1 = umin(k, b1); k = t;
    t = umax(k, b2); b2 = umin(k, b2); k = t;
    t = umax(k, b3); b3 = umin(k, b3); k = t;
    b4 = umin(k, b4);
}
#define GINS4(key, b1, b2, b3, b4) do { \
    uint32_t _k = (key); \
    if (_k < (b4)) ins4(_k, b1, b2, b3, b4); \
} while (0)

// ---------------------------------------------------------------------------
// Kernel 1: prep — enorm (warp-reduced), resets, bf16 codebook tile image
// ---------------------------------------------------------------------------
__global__ void vq_prep(const float* __restrict__ cb) {
    int w    = threadIdx.x >> 5;
    int lane = threadIdx.x & 31;
    int k    = blockIdx.x * 4 + w;              // 0..1023
    int c    = lane << 2;

    float4 v = ((const float4*)(cb + (size_t)k * CDIM))[lane];
    float s = __fmaf_rn(v.x, v.x, 0.f);
    s = __fmaf_rn(v.y, v.y, s);
    s = __fmaf_rn(v.z, v.z, s);
    s = __fmaf_rn(v.w, v.w, s);
    #pragma unroll
    for (int off = 16; off; off >>= 1)
        s = __fadd_rn(s, __shfl_down_sync(0xffffffffu, s, off));

    int nt = k >> 7, r = k & 127;
    uint8_t* img = (uint8_t*)g_cbh[nt] + toff(r, c);
    __nv_bfloat162 p0, p1;
    p0.x = __float2bfloat16(v.x); p0.y = __float2bfloat16(v.y);
    p1.x = __float2bfloat16(v.z); p1.y = __float2bfloat16(v.w);
    *(__nv_bfloat162*)(img)     = p0;
    *(__nv_bfloat162*)(img + 4) = p1;

    if (lane == 0) { g_enorm[k] = s; g_used[k] = 0; if (k == 0) g_sq = 0.0; }
}

// ---------------------------------------------------------------------------
// Kernel 2: main — bf16 mma.sync GEMM (A frags in regs, shared A/B smem),
//           keyed top-4 + exact 4-way rescue, 3 CTAs/SM
// ---------------------------------------------------------------------------
__global__ void __launch_bounds__(NTHREADS, 3) vq_mma(
    const float* __restrict__ z, const float* __restrict__ cb,
    float* __restrict__ out)
{
    extern __shared__ char smem[];
    const uint32_t sb = s2u(smem);
    const int tid  = threadIdx.x;
    const int w    = tid >> 5;
    const int lane = tid & 31;
    const int g    = lane >> 2;
    const int tg   = lane & 3;
    const int m0   = w << 4;

    float* se  = (float*)(smem + SM_SE);
    float* se1 = (float*)(smem + SM_SE1);
    float* vna = (float*)(smem + SM_VN);
    int*   rk  = (int*)(smem + SM_RK);
    int*   rne = (int*)(smem + SM_RNE);

    #pragma unroll
    for (int i = tid; i < KTOT; i += NTHREADS) {
        float e = g_enorm[i];
        se[i]  = e;
        se1[i] = __fadd_rn(e, 1.0f);
    }

    // ---- stage z into AB as swizzled bf16 A-image (exact z stays in GMEM) ----
    const int n0 = blockIdx.x * MV;
    const int b  = n0 >> 12;
    const int p0 = n0 & (HW - 1);
    const float* zb = z + (size_t)b * CDIM * HW + p0;
    uint8_t* ab = (uint8_t*)smem + SM_AB;
    #pragma unroll 4
    for (int idx = tid; idx < CDIM * MV; idx += NTHREADS) {
        int c = idx >> 7, v = idx & 127;
        float x = zb[(size_t)c * HW + v];
        *(__nv_bfloat16*)(ab + toff(v, c)) = __float2bfloat16(x);
    }

    // ||z||^2 per vector (exact ascending chain; coalesced GMEM reads)
    if (tid < MV) {
        float s = 0.f;
        #pragma unroll 8
        for (int c = 0; c < CDIM; ++c) {
            float x = zb[(size_t)c * HW + tid];
            s = __fmaf_rn(x, x, s);
        }
        vna[tid] = s;
    }
    __syncthreads();

    // ---- load A fragments ONCE (z static): 8 x ldmatrix.x4 ----
    uint32_t afr[8][4];
    {
        int mat = lane >> 3;
        int ar  = m0 + (lane & 7) + ((mat & 1) << 3);
        uint32_t arow = sb + SM_AB + ar * 256;
        #pragma unroll
        for (int kk = 0; kk < 8; ++kk) {
            int ac = (kk << 1) + (mat >> 1);
            uint32_t aaddr = arow + (((ac ^ (ar & 7))) << 4);
            asm volatile(
                "ldmatrix.sync.aligned.m8n8.x4.shared.b16 {%0,%1,%2,%3}, [%4];"
                : "=r"(afr[kk][0]), "=r"(afr[kk][1]),
                  "=r"(afr[kk][2]), "=r"(afr[kk][3]) : "r"(aaddr));
        }
    }
    __syncthreads();   // AB now free: becomes the per-tile B buffer

    // keyed top-4, rows L (m0+g) and H (m0+g+8)
    uint32_t L1 = 0xFFFFFFFFu, L2 = 0xFFFFFFFFu, L3 = 0xFFFFFFFFu, L4 = 0xFFFFFFFFu;
    uint32_t H1 = 0xFFFFFFFFu, H2 = 0xFFFFFFFFu, H3 = 0xFFFFFFFFu, H4 = 0xFFFFFFFFu;

    const int b_jhalf = (lane >> 4) & 1;
    const int b_kpar  = (lane >> 3) & 1;
    const int b_row   = lane & 7;

    for (int nt = 0; nt < NTILES; ++nt) {
        // ---- stage B tile image into AB (flat 32KB coalesced copy) ----
        {
            const uint4* sh = (const uint4*)g_cbh[nt];
            uint4* dh = (uint4*)(smem + SM_AB);
            #pragma unroll
            for (int i = tid; i < 2048; i += NTHREADS) dh[i] = sh[i];
        }
        __syncthreads();

        #pragma unroll 1
        for (int g32 = 0; g32 < 4; ++g32) {     // 32 codes per group
            float acc[4][4];
            #pragma unroll
            for (int j = 0; j < 4; ++j)
                #pragma unroll
                for (int q = 0; q < 4; ++q) acc[j][q] = 0.f;

            #pragma unroll
            for (int kk = 0; kk < 8; ++kk) {    // 8 k16 steps, B frags 8 regs live
                uint32_t bf[2][4];
                int bc = (kk << 1) + b_kpar;
                #pragma unroll
                for (int jp = 0; jp < 2; ++jp) {
                    int br = (g32 << 5) + (jp << 4) + (b_jhalf << 3) + b_row;
                    uint32_t baddr = sb + SM_AB + br * 256 + (((bc ^ (br & 7))) << 4);
                    asm volatile(
                        "ldmatrix.sync.aligned.m8n8.x4.shared.b16 {%0,%1,%2,%3}, [%4];"
                        : "=r"(bf[jp][0]), "=r"(bf[jp][1]),
                          "=r"(bf[jp][2]), "=r"(bf[jp][3]) : "r"(baddr));
                }
                #pragma unroll
                for (int j = 0; j < 4; ++j) {
                    const uint32_t* bp = &bf[j >> 1][(j & 1) << 1];
                    asm volatile(
                        "mma.sync.aligned.m16n8k16.row.col.f32.bf16.bf16.f32 "
                        "{%0,%1,%2,%3}, {%4,%5,%6,%7}, {%8,%9}, {%0,%1,%2,%3};"
                        : "+f"(acc[j][0]), "+f"(acc[j][1]),
                          "+f"(acc[j][2]), "+f"(acc[j][3])
                        : "r"(afr[kk][0]), "r"(afr[kk][1]),
                          "r"(afr[kk][2]), "r"(afr[kk][3]),
                          "r"(bp[0]), "r"(bp[1]));
                }
            }

            // ---- keyed approx ranking: r = (se+1) - 2*dot, guarded insert ----
            int kgb = nt * NTL + (g32 << 5);
            #pragma unroll
            for (int j = 0; j < 4; ++j) {
                int c0 = kgb + (j << 3) + (tg << 1);
                float s0 = se1[c0], s1 = se1[c0 + 1];
                GINS4(mkkey(__fmaf_rn(-2.f, acc[j][0], s0), c0),     L1, L2, L3, L4);
                GINS4(mkkey(__fmaf_rn(-2.f, acc[j][1], s1), c0 + 1), L1, L2, L3, L4);
                GINS4(mkkey(__fmaf_rn(-2.f, acc[j][2], s0), c0),     H1, H2, H3, H4);
                GINS4(mkkey(__fmaf_rn(-2.f, acc[j][3], s1), c0 + 1), H1, H2, H3, H4);
            }
        }
        __syncthreads();    // all warps done reading AB before next restage
    }

    // ---- merge top-4 across the 4 lanes of each quad ----
    #pragma unroll
    for (int d = 1; d <= 2; d <<= 1) {
        uint32_t o1 = __shfl_xor_sync(0xffffffffu, L1, d);
        uint32_t o2 = __shfl_xor_sync(0xffffffffu, L2, d);
        uint32_t o3 = __shfl_xor_sync(0xffffffffu, L3, d);
        uint32_t o4 = __shfl_xor_sync(0xffffffffu, L4, d);
        ins4(o1, L1, L2, L3, L4); ins4(o2, L1, L2, L3, L4);
        ins4(o3, L1, L2, L3, L4); ins4(o4, L1, L2, L3, L4);
        o1 = __shfl_xor_sync(0xffffffffu, H1, d);
        o2 = __shfl_xor_sync(0xffffffffu, H2, d);
        o3 = __shfl_xor_sync(0xffffffffu, H3, d);
        o4 = __shfl_xor_sync(0xffffffffu, H4, d);
        ins4(o1, H1, H2, H3, H4); ins4(o2, H1, H2, H3, H4);
        ins4(o3, H1, H2, H3, H4); ins4(o4, H1, H2, H3, H4);
    }
    if (tg == 0) {
        int rL = m0 + g, rH = m0 + g + 8;
        rk[rL * 4 + 0] = L1 & 1023; rk[rL * 4 + 1] = L2 & 1023;
        rk[rL * 4 + 2] = L3 & 1023; rk[rL * 4 + 3] = L4 & 1023;
        rk[rH * 4 + 0] = H1 & 1023; rk[rH * 4 + 1] = H2 & 1023;
        rk[rH * 4 + 2] = H3 & 1023; rk[rH * 4 + 3] = H4 & 1023;
        float sL1 = __uint_as_float(L1 & 0xFFFFFC00u);
        float sL2 = __uint_as_float(L2 & 0xFFFFFC00u);
        float sH1 = __uint_as_float(H1 & 0xFFFFFC00u);
        float sH2 = __uint_as_float(H2 & 0xFFFFFC00u);
        rne[rL] = (__fsub_rn(sL2, sL1) <= RESCUE_EPS);
        rne[rH] = (__fsub_rn(sH2, sH1) <= RESCUE_EPS);
    }
    __syncthreads();

    // ---- exact 4-way rescue (reference fp32 chain, z from GMEM) + output ----
    float errsum = 0.f;
    if (tid < MV) {
        int v = tid;
        int kb = rk[v * 4];
        if (rne[v]) {
            int k0 = rk[v * 4], k1 = rk[v * 4 + 1],
                k2 = rk[v * 4 + 2], k3 = rk[v * 4 + 3];
            const float* r0 = cb + (size_t)k0 * CDIM;
            const float* r1 = cb + (size_t)k1 * CDIM;
            const float* r2 = cb + (size_t)k2 * CDIM;
            const float* r3 = cb + (size_t)k3 * CDIM;
            float d0 = 0.f, d1 = 0.f, d2 = 0.f, d3 = 0.f;
            #pragma unroll 8
            for (int c = 0; c < CDIM; ++c) {
                float zv = zb[(size_t)c * HW + v];
                d0 = __fmaf_rn(zv, r0[c], d0);
                d1 = __fmaf_rn(zv, r1[c], d1);
                d2 = __fmaf_rn(zv, r2[c], d2);
                d3 = __fmaf_rn(zv, r3[c], d3);
            }
            float vn = vna[v];
            float e0 = __fsub_rn(__fadd_rn(vn, se[k0]), __fmul_rn(2.0f, d0));
            float e1 = __fsub_rn(__fadd_rn(vn, se[k1]), __fmul_rn(2.0f, d1));
            float e2 = __fsub_rn(__fadd_rn(vn, se[k2]), __fmul_rn(2.0f, d2));
            float e3 = __fsub_rn(__fadd_rn(vn, se[k3]), __fmul_rn(2.0f, d3));
            float bd = e0; kb = k0;
            if (e1 < bd || (e1 == bd && k1 < kb)) { bd = e1; kb = k1; }
            if (e2 < bd || (e2 == bd && k2 < kb)) { bd = e2; kb = k2; }
            if (e3 < bd || (e3 == bd && k3 < kb)) { bd = e3; kb = k3; }
        }
        g_used[kb] = 1;

        // z_q_st = fl(z + fl(z_q - z)) in (B,C,H,W); MSE partial
        const float4* crow = (const float4*)(cb + (size_t)kb * CDIM);
        float* ob = out + (size_t)b * CDIM * HW + p0 + v;
        #pragma unroll 4
        for (int c4 = 0; c4 < 32; ++c4) {
            float4 e4 = crow[c4];
            float ee[4] = {e4.x, e4.y, e4.z, e4.w};
            #pragma unroll
            for (int jj = 0; jj < 4; ++jj) {
                int c = c4 * 4 + jj;
                float zv = zb[(size_t)c * HW + v];
                float t  = __fsub_rn(ee[jj], zv);
                ob[(size_t)c * HW] = __fadd_rn(zv, t);
                errsum = __fmaf_rn(t, t, errsum);
            }
        }
    }

    // ---- block reduce squared error -> double atomic ----
    __syncthreads();
    float* red = (float*)(smem + SM_SE);
    if (tid < MV) red[tid] = errsum;
    __syncthreads();
    if (tid < 64) red[tid] = __fadd_rn(red[tid], red[tid + 64]);
    __syncthreads();
    if (tid < 32) {
        float s = __fadd_rn(red[tid], red[tid + 32]);
        #pragma unroll
        for (int off = 16; off; off >>= 1)
            s = __fadd_rn(s, __shfl_down_sync(0xffffffffu, s, off));
        if (tid == 0) atomicAdd(&g_sq, (double)s);
    }
}

// ---------------------------------------------------------------------------
// Kernel 3: finalize — vq_loss + usage scalars
// ---------------------------------------------------------------------------
__global__ void vq_fin(float* __restrict__ out, int npix) {
    __shared__ int cnt[32];
    int tid = threadIdx.x;             // 1024 threads
    int u = g_used[tid] ? 1 : 0;
    #pragma unroll
    for (int off = 16; off; off >>= 1) u += __shfl_down_sync(0xffffffffu, u, off);
    if ((tid & 31) == 0) cnt[tid >> 5] = u;
    __syncthreads();
    if (tid == 0) {
        int total = 0;
        #pragma unroll
        for (int i = 0; i < 32; ++i) total += cnt[i];
        float m  = (float)(g_sq / (double)npix);
        float vq = __fadd_rn(m, __fmul_rn(0.25f, m));
        out[npix]     = vq;
        out[npix + 1] = (float)total * (1.0f / 1024.0f);
    }
}

// ---------------------------------------------------------------------------
extern "C" void kernel_launch(void* const* d_in, const int* in_sizes, int n_in,
                              void* d_out, int out_size) {
    const float* z  = (const float*)d_in[0];
    const float* cb = (const float*)d_in[1];
    float* out = (float*)d_out;
    int npix = out_size - 2;                    // 8388608
    int nvec = npix / CDIM;                     // 65536
    int blocks = nvec / MV;                     // 512

    cudaFuncSetAttribute(vq_mma, cudaFuncAttributeMaxDynamicSharedMemorySize, SM_TOTAL);

    vq_prep<<<KTOT / 4, 128>>>(cb);
    vq_mma<<<blocks, NTHREADS, SM_TOTAL>>>(z, cb, out);
    vq_fin<<<1, KTOT>>>(out, npix);
}